// round 17
// baseline (speedup 1.0000x reference)
#include <cuda_runtime.h>
#include <math.h>

#define N_NODES 32768
#define DMODEL  512
#define NHEADS  8
#define HDIM    64
#define LN_EPS  1e-5f

// 64 MB scratch for attn [N, D] (device-global: allocation rules forbid cudaMalloc)
__device__ float g_attn[N_NODES * DMODEL];

// ---------------------------------------------------------------------------
// GEMM: C[M,512] = act(A[M,512] @ B[512,512]) (+ resid), M = 32768.
// BM=128, BN=128, BK=8, 256 threads, 8x8 register tile, double-buffered smem.
// ---------------------------------------------------------------------------
template<bool RELU, bool RESID>
__global__ __launch_bounds__(256, 2)
void gemm128(const float* __restrict__ A,
             const float* __restrict__ B,
             const float* __restrict__ resid,
             float* __restrict__ C)
{
    // As stride 132: conflict-free transposed STS, still 16B-aligned (132%4==0)
    __shared__ float As[2][8][132];
    __shared__ float Bs[2][8][128];

    const int tid  = threadIdx.x;
    const int tx   = tid & 15;          // 8 cols each
    const int ty   = tid >> 4;          // 8 rows each
    const int row0 = blockIdx.y * 128;
    const int col0 = blockIdx.x * 128;

    // global-load mapping
    const int arow = tid >> 1;          // 0..127
    const int aseg = tid & 1;           // 0..1  (float4)
    const int brow = tid >> 5;          // 0..7
    const int bseg = tid & 31;          // 0..31 (float4)

    const float* Ag = A + (long)(row0 + arow) * DMODEL + aseg * 4;
    const float* Bg = B + (long)brow * DMODEL + col0 + bseg * 4;

    float acc[8][8];
#pragma unroll
    for (int i = 0; i < 8; i++)
#pragma unroll
        for (int j = 0; j < 8; j++) acc[i][j] = 0.f;

    // preload k0 = 0 into buffer 0
    {
        float4 av = *(const float4*)Ag;
        float4 bv = *(const float4*)Bg;
        As[0][aseg * 4 + 0][arow] = av.x;
        As[0][aseg * 4 + 1][arow] = av.y;
        As[0][aseg * 4 + 2][arow] = av.z;
        As[0][aseg * 4 + 3][arow] = av.w;
        *(float4*)&Bs[0][brow][bseg * 4] = bv;
    }
    __syncthreads();

    int buf = 0;
    for (int k0 = 0; k0 < DMODEL; k0 += 8) {
        float4 av2, bv2;
        const bool more = (k0 + 8) < DMODEL;
        if (more) {
            av2 = *(const float4*)(Ag + k0 + 8);
            bv2 = *(const float4*)(Bg + (long)(k0 + 8) * DMODEL);
        }

#pragma unroll
        for (int kk = 0; kk < 8; kk++) {
            float a[8], b[8];
            *(float4*)&a[0] = *(float4*)&As[buf][kk][ty * 8];
            *(float4*)&a[4] = *(float4*)&As[buf][kk][ty * 8 + 4];
            *(float4*)&b[0] = *(float4*)&Bs[buf][kk][tx * 8];
            *(float4*)&b[4] = *(float4*)&Bs[buf][kk][tx * 8 + 4];
#pragma unroll
            for (int i = 0; i < 8; i++)
#pragma unroll
                for (int j = 0; j < 8; j++)
                    acc[i][j] += a[i] * b[j];
        }

        if (more) {
            const int nb = buf ^ 1;
            As[nb][aseg * 4 + 0][arow] = av2.x;
            As[nb][aseg * 4 + 1][arow] = av2.y;
            As[nb][aseg * 4 + 2][arow] = av2.z;
            As[nb][aseg * 4 + 3][arow] = av2.w;
            *(float4*)&Bs[nb][brow][bseg * 4] = bv2;
        }
        __syncthreads();
        buf ^= 1;
    }

#pragma unroll
    for (int i = 0; i < 8; i++) {
        const long r = row0 + ty * 8 + i;
#pragma unroll
        for (int jj = 0; jj < 2; jj++) {
            float4 o;
            o.x = acc[i][jj * 4 + 0];
            o.y = acc[i][jj * 4 + 1];
            o.z = acc[i][jj * 4 + 2];
            o.w = acc[i][jj * 4 + 3];
            if (RESID) {
                float4 hv = *(const float4*)&resid[r * DMODEL + col0 + tx * 8 + jj * 4];
                o.x += hv.x; o.y += hv.y; o.z += hv.z; o.w += hv.w;
            }
            if (RELU) {
                o.x = fmaxf(o.x, 0.f); o.y = fmaxf(o.y, 0.f);
                o.z = fmaxf(o.z, 0.f); o.w = fmaxf(o.w, 0.f);
            }
            *(float4*)&C[r * DMODEL + col0 + tx * 8 + jj * 4] = o;
        }
    }
}

// ---------------------------------------------------------------------------
// Per-node linear attention via head Gram matrix (algebraic reassociation):
//   S[h,h'] = q_h . k_h'            (8x8)
//   num[h]  = sum_h' S[h,h'] v_h'   denom[h] = sum_h' S[h,h']
//   attn[h] = num[h] / denom[h]
// 4 nodes per 256-thread block; 64 threads per node.
// q/k stored in smem with stride 68 -> S-phase LDS conflict-free.
// ---------------------------------------------------------------------------
#define QK_STRIDE 68

__global__ __launch_bounds__(256, 8)
void attn_kernel(const float* __restrict__ q,
                 const float* __restrict__ k,
                 const float* __restrict__ v)
{
    __shared__ float sq[4][NHEADS][QK_STRIDE];
    __shared__ float sk[4][NHEADS][QK_STRIDE];
    __shared__ float sv[4][DMODEL];
    __shared__ float sS[4][NHEADS * NHEADS];

    const int tid = threadIdx.x;
    const int n   = tid >> 6;            // node slot 0..3
    const int t   = tid & 63;            // lane within node
    const long node = (long)blockIdx.x * 4 + n;
    const long base = node * DMODEL;

    // load q,k (padded) and v (flat), float4 each, 2 iters per array
#pragma unroll
    for (int j = 0; j < 2; j++) {
        const int idx  = t + j * 64;     // float4 index 0..127
        const int elem = idx * 4;
        const int hh   = elem >> 6;
        const int dd   = elem & 63;
        float4 qv = *(const float4*)&q[base + elem];
        float4 kv4 = *(const float4*)&k[base + elem];
        float4 vv = *(const float4*)&v[base + elem];
        *(float4*)&sq[n][hh][dd] = qv;
        *(float4*)&sk[n][hh][dd] = kv4;
        *(float4*)&sv[n][elem]   = vv;
    }
    __syncthreads();

    // S[h][g] = q_h . k_g  (thread t -> h = t>>3, g = t&7)
    {
        const int hh = t >> 3;
        const int gg = t & 7;
        float s = 0.f;
#pragma unroll
        for (int d = 0; d < HDIM; d++)
            s += sq[n][hh][d] * sk[n][gg][d];
        sS[n][t] = s;
    }
    __syncthreads();

    // thread t = column e: attn[h][e] = (sum_g S[h][g] v[g][e]) / (sum_g S[h][g])
#pragma unroll
    for (int hh = 0; hh < NHEADS; hh++) {
        float num = 0.f, den = 0.f;
#pragma unroll
        for (int gg = 0; gg < NHEADS; gg++) {
            const float s = sS[n][hh * 8 + gg];   // broadcast
            num += s * sv[n][gg * HDIM + t];
            den += s;
        }
        g_attn[base + hh * HDIM + t] = num / den;
    }
}

// ---------------------------------------------------------------------------
// In-place LayerNorm over out[N,512]: one warp per row, 16 floats per lane.
// ---------------------------------------------------------------------------
__global__ __launch_bounds__(256, 8)
void ln_kernel(float* __restrict__ out,
               const float* __restrict__ gamma,
               const float* __restrict__ beta)
{
    const int warp = threadIdx.x >> 5;
    const int lane = threadIdx.x & 31;
    const long row = (long)blockIdx.x * 8 + warp;
    float* p = out + row * DMODEL;

    float4 x[4];
#pragma unroll
    for (int j = 0; j < 4; j++)
        x[j] = *(const float4*)&p[(j * 32 + lane) * 4];

    float s = 0.f;
#pragma unroll
    for (int j = 0; j < 4; j++) s += x[j].x + x[j].y + x[j].z + x[j].w;
#pragma unroll
    for (int o = 16; o > 0; o >>= 1) s += __shfl_xor_sync(0xffffffffu, s, o);
    const float mean = s * (1.0f / DMODEL);

    float vs = 0.f;
#pragma unroll
    for (int j = 0; j < 4; j++) {
        float dx = x[j].x - mean; vs += dx * dx;
        dx = x[j].y - mean; vs += dx * dx;
        dx = x[j].z - mean; vs += dx * dx;
        dx = x[j].w - mean; vs += dx * dx;
    }
#pragma unroll
    for (int o = 16; o > 0; o >>= 1) vs += __shfl_xor_sync(0xffffffffu, vs, o);
    const float rstd = rsqrtf(vs * (1.0f / DMODEL) + LN_EPS);

#pragma unroll
    for (int j = 0; j < 4; j++) {
        const int c = (j * 32 + lane) * 4;
        float4 gv = *(const float4*)&gamma[c];
        float4 bv = *(const float4*)&beta[c];
        float4 o4;
        o4.x = (x[j].x - mean) * rstd * gv.x + bv.x;
        o4.y = (x[j].y - mean) * rstd * gv.y + bv.y;
        o4.z = (x[j].z - mean) * rstd * gv.z + bv.z;
        o4.w = (x[j].w - mean) * rstd * gv.w + bv.w;
        *(float4*)&p[c] = o4;
    }
}

// ---------------------------------------------------------------------------
// Launch. Inputs: h, Wq, Wk, Wv, Wf, ln_gamma, ln_beta.
// Output tuple (out, q, k, v): [N*D | N*D | N*D | N*D].
// ---------------------------------------------------------------------------
extern "C" void kernel_launch(void* const* d_in, const int* in_sizes, int n_in,
                              void* d_out, int out_size)
{
    const float* h     = (const float*)d_in[0];
    const float* Wq    = (const float*)d_in[1];
    const float* Wk    = (const float*)d_in[2];
    const float* Wv    = (const float*)d_in[3];
    const float* Wf    = (const float*)d_in[4];
    const float* gamma = (const float*)d_in[5];
    const float* beta  = (const float*)d_in[6];

    float* out = (float*)d_out;
    float* q   = out + (long)N_NODES * DMODEL;
    float* k   = out + 2L * N_NODES * DMODEL;
    float* v   = out + 3L * N_NODES * DMODEL;

    float* attn_ptr = nullptr;
    cudaGetSymbolAddress((void**)&attn_ptr, g_attn);

    dim3 gg(DMODEL / 128, N_NODES / 128);   // (4, 256)

    gemm128<true,  false><<<gg, 256>>>(h, Wq, nullptr, q);
    gemm128<true,  false><<<gg, 256>>>(h, Wk, nullptr, k);
    gemm128<false, false><<<gg, 256>>>(h, Wv, nullptr, v);

    attn_kernel<<<N_NODES / 4, 256>>>(q, k, v);

    gemm128<false, true><<<gg, 256>>>(attn_ptr, Wf, h, out);

    ln_kernel<<<N_NODES / 8, 256>>>(out, gamma, beta);
}